// round 3
// baseline (speedup 1.0000x reference)
#include <cuda_runtime.h>

#define B_   256
#define T_   100
#define NIN  700
#define NN   2068
#define NOUT 20
#define TAU  0.6f
#define KC   320      // Eigen kc panel size (320 cap in blocking heuristic)

// ---------------- scratch (device globals; no runtime allocation) ----------
__device__ float g_ff[(size_t)T_ * B_ * NN];   // [T, B, N] feedforward drive
__device__ float g_w1t[(size_t)NIN * NN];      // W_fc1 transposed -> [K, N]
__device__ float g_mem[(size_t)B_ * NN];       // membrane state
__device__ float g_spk[(size_t)B_ * NN];       // spike state (0/1 as float)

// ---------------- init ------------------------------------------------------
__global__ void zero_state_kernel() {
    int i = blockIdx.x * blockDim.x + threadIdx.x;
    if (i < B_ * NN) { g_mem[i] = 0.0f; g_spk[i] = 0.0f; }
}

__global__ void transpose_w1_kernel(const float* __restrict__ W1) {
    int idx = blockIdx.x * blockDim.x + threadIdx.x;
    if (idx < NIN * NN) {
        int k = idx / NN;
        int n = idx - k * NN;
        g_w1t[idx] = W1[(size_t)n * NIN + k];   // W1 is [N, K] row-major
    }
}

// ---------------- phase 1: ff = x @ W_fc1^T ---------------------------------
// Eigen-exact order per output element:
//   tot = 0;  for each kc=320 panel (ascending): tot = fadd(tot, seq-fma over panel)
#define BM 128
#define BN 128
#define BK 16

__global__ __launch_bounds__(256) void gemm_ff_kernel(const float* __restrict__ x) {
    __shared__ float As[BK][BM];
    __shared__ float Bs[BK][BN];

    int tid  = threadIdx.x;
    int row0 = blockIdx.y * BM;
    int col0 = blockIdx.x * BN;

    int arow = tid >> 1;
    int asub = (tid & 1) * 8;
    int r    = row0 + arow;
    int tt   = r >> 8;                      // r = t*B + b, B_=256
    int bb   = r & 255;
    const float* xrow = x + ((size_t)bb * T_ + tt) * NIN;

    int bn   = tid & 127;
    int bsub = (tid >> 7) * 8;
    int gn   = col0 + bn;

    int tr = (tid >> 4) * 8;
    int tc = (tid & 15) * 8;

    float tot[8][8];
    float pac[8][8];
    #pragma unroll
    for (int i = 0; i < 8; i++)
        #pragma unroll
        for (int j = 0; j < 8; j++) tot[i][j] = 0.0f;

    for (int p0 = 0; p0 < NIN; p0 += KC) {          // panels: [0,320),[320,640),[640,700)
        int pend = (p0 + KC < NIN) ? (p0 + KC) : NIN;

        #pragma unroll
        for (int i = 0; i < 8; i++)
            #pragma unroll
            for (int j = 0; j < 8; j++) pac[i][j] = 0.0f;

        for (int k0 = p0; k0 < pend; k0 += BK) {    // 320 % 16 == 0: chunks never straddle panels
            #pragma unroll
            for (int i = 0; i < 8; i++) {
                int k = k0 + asub + i;
                As[asub + i][arow] = (k < pend) ? xrow[k] : 0.0f;
            }
            #pragma unroll
            for (int i = 0; i < 8; i++) {
                int k = k0 + bsub + i;
                Bs[bsub + i][bn] = (k < pend && gn < NN) ? g_w1t[(size_t)k * NN + gn] : 0.0f;
            }
            __syncthreads();

            #pragma unroll
            for (int kk = 0; kk < BK; kk++) {
                float a[8], bv[8];
                #pragma unroll
                for (int i = 0; i < 8; i++) a[i]  = As[kk][tr + i];
                #pragma unroll
                for (int j = 0; j < 8; j++) bv[j] = Bs[kk][tc + j];
                #pragma unroll
                for (int i = 0; i < 8; i++)
                    #pragma unroll
                    for (int j = 0; j < 8; j++)
                        pac[i][j] = __fmaf_rn(a[i], bv[j], pac[i][j]);  // seq-k, fma(0,..) exact no-op
            }
            __syncthreads();
        }

        #pragma unroll
        for (int i = 0; i < 8; i++)
            #pragma unroll
            for (int j = 0; j < 8; j++)
                tot[i][j] = __fadd_rn(tot[i][j], pac[i][j]);           // C += panel
    }

    #pragma unroll
    for (int i = 0; i < 8; i++) {
        size_t rr = (size_t)(row0 + tr + i);
        #pragma unroll
        for (int j = 0; j < 8; j++) {
            int n = col0 + tc + j;
            if (n < NN) g_ff[rr * NN + n] = tot[i][j];
        }
    }
}

// ---------------- phase 2: one LIF timestep ---------------------------------
// rec per element: panels of 320 over presynaptic index m; within a panel,
// sequential adds of active rows (fma(1,w,acc)==fadd); across panels C += p.
// Then: cur = fadd(ff, rec); mem = fadd(fmul(fmul(TAU,mem),fsub(1,spk)), cur).
#define CPT 9   // ceil(2068/256)

__global__ __launch_bounds__(256) void step_kernel(const float* __restrict__ Wrec,
                                                   float* __restrict__ out, int t) {
    __shared__ int s_act[NN];
    __shared__ int s_cnt;

    int b   = blockIdx.x;
    int tid = threadIdx.x;

    float*       mem_row = g_mem + (size_t)b * NN;
    float*       spk_row = g_spk + (size_t)b * NN;
    const float* ff_row  = g_ff + ((size_t)t * B_ + b) * NN;

    // Warp 0 builds the ascending active-neuron list (deterministic order).
    if (tid < 32) {
        int cnt = 0;
        for (int base = 0; base < NN; base += 32) {
            int  m = base + tid;
            bool a = (m < NN) && (spk_row[m] != 0.0f);
            unsigned mask = __ballot_sync(0xffffffffu, a);
            if (a) s_act[cnt + __popc(mask & ((1u << tid) - 1u))] = m;
            cnt += __popc(mask);
        }
        if (tid == 0) s_cnt = cnt;
    }
    __syncthreads();
    int cnt = s_cnt;

    float rec[CPT], part[CPT];
    #pragma unroll
    for (int j = 0; j < CPT; j++) { rec[j] = 0.0f; part[j] = 0.0f; }

    int curPanel = 0;
    for (int i = 0; i < cnt; i++) {
        int m = s_act[i];
        int p = m / KC;
        if (p != curPanel) {                       // flush previous panel partial
            #pragma unroll
            for (int j = 0; j < CPT; j++) {
                rec[j]  = __fadd_rn(rec[j], part[j]);
                part[j] = 0.0f;
            }
            curPanel = p;
        }
        const float* wr = Wrec + (size_t)m * NN;
        #pragma unroll
        for (int j = 0; j < CPT; j++) {
            int n = tid + j * 256;
            if (n < NN) part[j] = __fadd_rn(part[j], wr[n]);
        }
    }
    #pragma unroll
    for (int j = 0; j < CPT; j++) rec[j] = __fadd_rn(rec[j], part[j]);  // final flush

    #pragma unroll
    for (int j = 0; j < CPT; j++) {
        int n = tid + j * 256;
        if (n < NN) {
            float cur = __fadd_rn(ff_row[n], rec[j]);
            float mo  = mem_row[n];
            float so  = spk_row[n];
            float t1  = __fmul_rn(TAU, mo);
            float t2  = __fsub_rn(1.0f, so);
            float t3  = __fmul_rn(t1, t2);
            float mn  = __fadd_rn(t3, cur);
            float sn  = (mn >= 1.0f) ? 1.0f : 0.0f;
            mem_row[n] = mn;
            spk_row[n] = sn;
            if (n >= NN - NOUT)
                out[((size_t)b * T_ + t) * NOUT + (n - (NN - NOUT))] = sn;
        }
    }
}

// ---------------- launch -----------------------------------------------------
extern "C" void kernel_launch(void* const* d_in, const int* in_sizes, int n_in,
                              void* d_out, int out_size) {
    const float* x  = (const float*)d_in[0];   // [B, T, NIN]
    const float* W1 = (const float*)d_in[1];   // [NN, NIN]
    const float* Wr = (const float*)d_in[2];   // [NN, NN]
    float* out = (float*)d_out;                // [B, T, NOUT]

    zero_state_kernel<<<(B_ * NN + 255) / 256, 256>>>();
    transpose_w1_kernel<<<(NIN * NN + 255) / 256, 256>>>(W1);

    dim3 ggrid((NN + BN - 1) / BN, (B_ * T_) / BM);   // 17 x 200
    gemm_ff_kernel<<<ggrid, 256>>>(x);

    for (int t = 0; t < T_; t++)
        step_kernel<<<B_, 256>>>(Wr, out, t);
}

// round 5
// speedup vs baseline: 2.2808x; 2.2808x over previous
#include <cuda_runtime.h>

#define B_   256
#define T_   100
#define NIN  700
#define KP   704            // NIN padded to multiple of 16
#define NN   2068
#define NNP  2176           // NN padded to multiple of 128
#define NOUT 20
#define TAU  0.6f
#define KC   320            // Eigen kc panel size
#define MROWS (B_ * T_)     // 25600

// ---------------- scratch (device globals; no runtime allocation) ----------
__device__ float g_ffp[3][(size_t)MROWS * NNP];  // per-panel ff partials
__device__ float g_xp[(size_t)MROWS * KP];       // x staged: [r = t*B+b][k], zero-padded
__device__ float g_w1t[(size_t)KP * NNP];        // W_fc1^T zero-padded: [k][n]

// ---------------- staging ---------------------------------------------------
__global__ void pad_x_kernel(const float* __restrict__ x) {
    size_t idx = (size_t)blockIdx.x * blockDim.x + threadIdx.x;
    if (idx < (size_t)MROWS * KP) {
        int r = (int)(idx / KP);
        int k = (int)(idx - (size_t)r * KP);
        int t = r >> 8;                 // r = t*256 + b
        int b = r & 255;
        g_xp[idx] = (k < NIN) ? x[((size_t)b * T_ + t) * NIN + k] : 0.0f;
    }
}

__global__ void pad_w1t_kernel(const float* __restrict__ W1) {
    size_t idx = (size_t)blockIdx.x * blockDim.x + threadIdx.x;
    if (idx < (size_t)KP * NNP) {
        int k = (int)(idx / NNP);
        int n = (int)(idx - (size_t)k * NNP);
        g_w1t[idx] = (k < NIN && n < NN) ? W1[(size_t)n * NIN + k] : 0.0f;
    }
}

// ---------------- phase 1: per-panel GEMM slabs ------------------------------
// Slab z: K range [z*320, z*320+KL), KL = 320,320,64(zero-padded 640..704).
// Single sequential-k FMA accumulator per element == Eigen in-panel order.
#define BM 128
#define BN 128
#define BK 16

__global__ __launch_bounds__(256, 2) void gemm_slab_kernel() {
    __shared__ float As[BK][BM];
    __shared__ float Bs[BK][BN];

    int tid  = threadIdx.x;
    int z    = blockIdx.z;
    int row0 = blockIdx.y * BM;
    int col0 = blockIdx.x * BN;
    int k0g  = z * KC;
    int KL   = (z == 2) ? (KP - 2 * KC) : KC;

    float* C = g_ffp[0] + (size_t)z * MROWS * NNP;

    int arow = tid >> 1;
    int asub = (tid & 1) * 8;
    const float* arow_p = g_xp + (size_t)(row0 + arow) * KP + k0g;

    int bn   = tid & 127;
    int bsub = (tid >> 7) * 8;
    const float* bcol_p = g_w1t + (size_t)k0g * NNP + (col0 + bn);

    int tr = (tid >> 4) * 8;
    int tc = (tid & 15) * 8;

    float acc[8][8];
    #pragma unroll
    for (int i = 0; i < 8; i++)
        #pragma unroll
        for (int j = 0; j < 8; j++) acc[i][j] = 0.0f;

    for (int k0 = 0; k0 < KL; k0 += BK) {
        // A tile: 2 x float4 global loads, scalar smem stores (As is k-major)
        float4 a0 = *(const float4*)(arow_p + k0 + asub);
        float4 a1 = *(const float4*)(arow_p + k0 + asub + 4);
        As[asub + 0][arow] = a0.x; As[asub + 1][arow] = a0.y;
        As[asub + 2][arow] = a0.z; As[asub + 3][arow] = a0.w;
        As[asub + 4][arow] = a1.x; As[asub + 5][arow] = a1.y;
        As[asub + 6][arow] = a1.z; As[asub + 7][arow] = a1.w;

        #pragma unroll
        for (int i = 0; i < 8; i++)
            Bs[bsub + i][bn] = bcol_p[(size_t)(k0 + bsub + i) * NNP];
        __syncthreads();

        #pragma unroll
        for (int kk = 0; kk < BK; kk++) {
            float a[8], bv[8];
            *(float4*)&a[0]  = *(const float4*)&As[kk][tr];
            *(float4*)&a[4]  = *(const float4*)&As[kk][tr + 4];
            *(float4*)&bv[0] = *(const float4*)&Bs[kk][tc];
            *(float4*)&bv[4] = *(const float4*)&Bs[kk][tc + 4];
            #pragma unroll
            for (int i = 0; i < 8; i++)
                #pragma unroll
                for (int j = 0; j < 8; j++)
                    acc[i][j] = __fmaf_rn(a[i], bv[j], acc[i][j]);
        }
        __syncthreads();
    }

    #pragma unroll
    for (int i = 0; i < 8; i++) {
        float* crow = C + (size_t)(row0 + tr + i) * NNP + (col0 + tc);
        *(float4*)(crow)     = *(float4*)&acc[i][0];
        *(float4*)(crow + 4) = *(float4*)&acc[i][4];
    }
}

// ---------------- phase 2: fused 100-step LIF, one CTA per batch -------------
// State lives in registers for the whole sequence. Per step:
//   ff  = fadd(fadd(p0,p1),p2)            (Eigen panel fold of ff GEMM)
//   rec = kc=320-panel fold of ascending active-row adds
//   cur = fadd(ff, rec); mem = fadd(fmul(fmul(TAU,mem),fsub(1,spk)),cur); spk = mem>=1
#define CPT 9   // j=0..7 full (n=tid+j*256), j=8 only tid<20 (n=2048..2067)

__global__ __launch_bounds__(256) void steps_kernel(const float* __restrict__ Wrec,
                                                    float* __restrict__ out) {
    __shared__ int s_list[NN];
    __shared__ int s_wcnt[CPT][8];

    int b    = blockIdx.x;
    int tid  = threadIdx.x;
    int wid  = tid >> 5;
    int lane = tid & 31;
    unsigned ltmask = (1u << lane) - 1u;

    float m[CPT], s[CPT];
    #pragma unroll
    for (int j = 0; j < CPT; j++) { m[j] = 0.0f; s[j] = 0.0f; }

    const float* ff0 = g_ffp[0];
    const float* ff1 = g_ffp[1];
    const float* ff2 = g_ffp[2];

    for (int t = 0; t < T_; t++) {
        // ---- build ascending active list (ballot + cross-warp prefix) ----
        unsigned msk[CPT];
        #pragma unroll
        for (int j = 0; j < CPT; j++) {
            bool a = ((j < 8) || (tid < NOUT)) && (s[j] != 0.0f);
            msk[j] = __ballot_sync(0xffffffffu, a);
            if (lane == 0) s_wcnt[j][wid] = __popc(msk[j]);
        }
        __syncthreads();

        int basejw[CPT];
        int cnt;
        {
            int rb = 0;
            #pragma unroll
            for (int jj = 0; jj < CPT; jj++) {
                int off = 0, rowtot = 0;
                #pragma unroll
                for (int w = 0; w < 8; w++) {
                    int c = s_wcnt[jj][w];
                    if (w < wid) off += c;
                    rowtot += c;
                }
                basejw[jj] = rb + off;
                rb += rowtot;
            }
            cnt = rb;
        }

        #pragma unroll
        for (int j = 0; j < CPT; j++) {
            bool a = ((j < 8) || (tid < NOUT)) && (s[j] != 0.0f);
            if (a) s_list[basejw[j] + __popc(msk[j] & ltmask)] = j * 256 + tid;
        }
        __syncthreads();

        // ---- prefetch ff partials (independent of rec loop) ----
        size_t rbase = ((size_t)t * B_ + b) * NNP;
        float f0[CPT], f1[CPT], f2[CPT];
        #pragma unroll
        for (int j = 0; j < CPT; j++) {
            int n = j * 256 + tid;
            bool v = (j < 8) || (tid < NOUT);
            f0[j] = v ? ff0[rbase + n] : 0.0f;
            f1[j] = v ? ff1[rbase + n] : 0.0f;
            f2[j] = v ? ff2[rbase + n] : 0.0f;
        }

        // ---- rec: panel-folded ascending adds of active W_rec rows ----
        float rec[CPT], part[CPT];
        #pragma unroll
        for (int j = 0; j < CPT; j++) { rec[j] = 0.0f; part[j] = 0.0f; }

        int curp = 0;
        for (int i = 0; i < cnt; i++) {
            int mrow = s_list[i];
            int p = mrow / KC;
            if (p != curp) {
                #pragma unroll
                for (int j = 0; j < CPT; j++) {
                    rec[j]  = __fadd_rn(rec[j], part[j]);
                    part[j] = 0.0f;
                }
                curp = p;
            }
            const float* wr = Wrec + (size_t)mrow * NN;
            #pragma unroll
            for (int j = 0; j < CPT; j++) {
                int n = j * 256 + tid;
                if ((j < 8) || (tid < NOUT))
                    part[j] = __fadd_rn(part[j], wr[n]);
            }
        }
        #pragma unroll
        for (int j = 0; j < CPT; j++) rec[j] = __fadd_rn(rec[j], part[j]);

        // ---- membrane update + spikes ----
        #pragma unroll
        for (int j = 0; j < CPT; j++) {
            if ((j < 8) || (tid < NOUT)) {
                float ffv = __fadd_rn(__fadd_rn(f0[j], f1[j]), f2[j]);
                float cur = __fadd_rn(ffv, rec[j]);
                float t1  = __fmul_rn(TAU, m[j]);
                float t2  = __fsub_rn(1.0f, s[j]);
                float t3  = __fmul_rn(t1, t2);
                float mn  = __fadd_rn(t3, cur);
                m[j] = mn;
                s[j] = (mn >= 1.0f) ? 1.0f : 0.0f;
            }
        }
        if (tid < NOUT)
            out[((size_t)b * T_ + t) * NOUT + tid] = s[8];

        __syncthreads();   // protect s_list/s_wcnt reuse next step
    }
}

// ---------------- launch -----------------------------------------------------
extern "C" void kernel_launch(void* const* d_in, const int* in_sizes, int n_in,
                              void* d_out, int out_size) {
    const float* x  = (const float*)d_in[0];   // [B, T, NIN]
    const float* W1 = (const float*)d_in[1];   // [NN, NIN]
    const float* Wr = (const float*)d_in[2];   // [NN, NN]
    float* out = (float*)d_out;                // [B, T, NOUT]

    {
        size_t n = (size_t)MROWS * KP;
        pad_x_kernel<<<(unsigned)((n + 255) / 256), 256>>>(x);
    }
    {
        size_t n = (size_t)KP * NNP;
        pad_w1t_kernel<<<(unsigned)((n + 255) / 256), 256>>>(W1);
    }

    dim3 ggrid(NNP / BN, MROWS / BM, 3);   // 17 x 200 x 3 slabs
    gemm_slab_kernel<<<ggrid, 256>>>();

    steps_kernel<<<B_, 256>>>(Wr, out);
}

// round 6
// speedup vs baseline: 2.8931x; 1.2684x over previous
#include <cuda_runtime.h>

#define B_   256
#define T_   100
#define NIN  700
#define KP   704            // NIN padded to multiple of 16
#define NN   2068
#define NNP  2176           // NN padded to multiple of 128
#define NOUT 20
#define TAU  0.6f
#define KC   320            // Eigen kc panel size
#define MROWS (B_ * T_)     // 25600

// ---------------- scratch (device globals; no runtime allocation) ----------
__device__ float g_ffp[3][(size_t)MROWS * NNP];  // per-panel ff partials
__device__ float g_xp[(size_t)MROWS * KP];       // x staged: [r = t*B+b][k], zero-padded
__device__ float g_w1t[(size_t)KP * NNP];        // W_fc1^T zero-padded: [k][n]

// ---------------- staging ---------------------------------------------------
__global__ void pad_x_kernel(const float* __restrict__ x) {
    size_t idx = (size_t)blockIdx.x * blockDim.x + threadIdx.x;
    if (idx < (size_t)MROWS * KP) {
        int r = (int)(idx / KP);
        int k = (int)(idx - (size_t)r * KP);
        int t = r >> 8;                 // r = t*256 + b
        int b = r & 255;
        g_xp[idx] = (k < NIN) ? x[((size_t)b * T_ + t) * NIN + k] : 0.0f;
    }
}

__global__ void pad_w1t_kernel(const float* __restrict__ W1) {
    size_t idx = (size_t)blockIdx.x * blockDim.x + threadIdx.x;
    if (idx < (size_t)KP * NNP) {
        int k = (int)(idx / NNP);
        int n = (int)(idx - (size_t)k * NNP);
        g_w1t[idx] = (k < NIN && n < NN) ? W1[(size_t)n * NIN + k] : 0.0f;
    }
}

// ---------------- phase 1: per-panel GEMM slabs (double-buffered) -----------
// Slab z: K range [z*320, z*320+KL), KL = 320,320,64(zero-padded 640..704).
// Single sequential-k FMA accumulator per element == Eigen in-panel order.
#define BM 128
#define BN 128
#define BK 16

__global__ __launch_bounds__(256, 2) void gemm_slab_kernel() {
    __shared__ float As[2][BK][BM];
    __shared__ float Bs[2][BK][BN];

    int tid  = threadIdx.x;
    int z    = blockIdx.z;
    int row0 = blockIdx.y * BM;
    int col0 = blockIdx.x * BN;
    int k0g  = z * KC;
    int KL   = (z == 2) ? (KP - 2 * KC) : KC;
    int nT   = KL / BK;

    float* C = g_ffp[0] + (size_t)z * MROWS * NNP;

    int arow = tid >> 1;
    int asub = (tid & 1) * 8;
    const float* ap = g_xp + (size_t)(row0 + arow) * KP + k0g + asub;

    int bn   = tid & 127;
    int bsub = (tid >> 7) * 8;
    const float* bp = g_w1t + (size_t)(k0g + bsub) * NNP + (col0 + bn);

    int tr = (tid >> 4) * 8;
    int tc = (tid & 15) * 8;

    float4 ra0, ra1;
    float  rbv[8];

    // prolog: load tile 0 into regs, stage into buffer 0
    ra0 = *(const float4*)(ap);
    ra1 = *(const float4*)(ap + 4);
    #pragma unroll
    for (int i = 0; i < 8; i++) rbv[i] = bp[(size_t)i * NNP];

    As[0][asub + 0][arow] = ra0.x; As[0][asub + 1][arow] = ra0.y;
    As[0][asub + 2][arow] = ra0.z; As[0][asub + 3][arow] = ra0.w;
    As[0][asub + 4][arow] = ra1.x; As[0][asub + 5][arow] = ra1.y;
    As[0][asub + 6][arow] = ra1.z; As[0][asub + 7][arow] = ra1.w;
    #pragma unroll
    for (int i = 0; i < 8; i++) Bs[0][bsub + i][bn] = rbv[i];
    __syncthreads();

    float acc[8][8];
    #pragma unroll
    for (int i = 0; i < 8; i++)
        #pragma unroll
        for (int j = 0; j < 8; j++) acc[i][j] = 0.0f;

    for (int tI = 0; tI < nT; tI++) {
        int  buf  = tI & 1;
        bool more = (tI + 1 < nT);

        if (more) {                               // prefetch next tile to regs
            const float* apn = ap + (tI + 1) * BK;
            ra0 = *(const float4*)(apn);
            ra1 = *(const float4*)(apn + 4);
            const float* bpn = bp + (size_t)(tI + 1) * BK * NNP;
            #pragma unroll
            for (int i = 0; i < 8; i++) rbv[i] = bpn[(size_t)i * NNP];
        }

        #pragma unroll
        for (int kk = 0; kk < BK; kk++) {
            float a[8], bv[8];
            *(float4*)&a[0]  = *(const float4*)&As[buf][kk][tr];
            *(float4*)&a[4]  = *(const float4*)&As[buf][kk][tr + 4];
            *(float4*)&bv[0] = *(const float4*)&Bs[buf][kk][tc];
            *(float4*)&bv[4] = *(const float4*)&Bs[buf][kk][tc + 4];
            #pragma unroll
            for (int i = 0; i < 8; i++)
                #pragma unroll
                for (int j = 0; j < 8; j++)
                    acc[i][j] = __fmaf_rn(a[i], bv[j], acc[i][j]);
        }

        if (more) {                               // stage next tile
            int nb = buf ^ 1;
            As[nb][asub + 0][arow] = ra0.x; As[nb][asub + 1][arow] = ra0.y;
            As[nb][asub + 2][arow] = ra0.z; As[nb][asub + 3][arow] = ra0.w;
            As[nb][asub + 4][arow] = ra1.x; As[nb][asub + 5][arow] = ra1.y;
            As[nb][asub + 6][arow] = ra1.z; As[nb][asub + 7][arow] = ra1.w;
            #pragma unroll
            for (int i = 0; i < 8; i++) Bs[nb][bsub + i][bn] = rbv[i];
        }
        __syncthreads();
    }

    #pragma unroll
    for (int i = 0; i < 8; i++) {
        float* crow = C + (size_t)(row0 + tr + i) * NNP + (col0 + tc);
        *(float4*)(crow)     = *(float4*)&acc[i][0];
        *(float4*)(crow + 4) = *(float4*)&acc[i][4];
    }
}

// ---------------- phase 2: fused 100-step LIF, one CTA per batch -------------
// 512 threads; thread covers n = j*512+tid, j=0..3 full, j=4 only tid<20.
// Per step (bitwise == reference):
//   ff  = fadd(fadd(p0,p1),p2)
//   rec = kc=320-panel fold of ascending active-row adds (unroll-4 gather)
//   cur = fadd(ff,rec); mem = fadd(fmul(fmul(TAU,mem),fsub(1,spk)),cur); spk = mem>=1
#define NT   512
#define SCPT 5
#define NWP  16

__device__ __forceinline__ void flush_panel(float* rec, float* part) {
    #pragma unroll
    for (int j = 0; j < SCPT; j++) {
        rec[j]  = __fadd_rn(rec[j], part[j]);
        part[j] = 0.0f;
    }
}
__device__ __forceinline__ void add_row(float* part, const float* v) {
    #pragma unroll
    for (int j = 0; j < SCPT; j++) part[j] = __fadd_rn(part[j], v[j]);
}

__global__ __launch_bounds__(NT, 2) void steps_kernel(const float* __restrict__ Wrec,
                                                      float* __restrict__ out) {
    __shared__ int s_list[NN];
    __shared__ int s_wcnt[SCPT][NWP];

    int b    = blockIdx.x;
    int tid  = threadIdx.x;
    int wid  = tid >> 5;
    int lane = tid & 31;
    unsigned ltmask = (1u << lane) - 1u;
    bool tv  = (tid < NOUT);

    float m[SCPT], s[SCPT];
    #pragma unroll
    for (int j = 0; j < SCPT; j++) { m[j] = 0.0f; s[j] = 0.0f; }

    const float* ff0 = g_ffp[0];
    const float* ff1 = g_ffp[1];
    const float* ff2 = g_ffp[2];

    for (int t = 0; t < T_; t++) {
        // ---- ff partial fold (independent loads, issued first) ----
        size_t rbase = ((size_t)t * B_ + b) * NNP;
        float ffv[SCPT];
        #pragma unroll
        for (int j = 0; j < SCPT; j++) {
            int n = j * NT + tid;
            bool v = (j < 4) || tv;
            ffv[j] = v ? __fadd_rn(__fadd_rn(ff0[rbase + n], ff1[rbase + n]), ff2[rbase + n])
                       : 0.0f;
        }

        // ---- build ascending active list (ballot + cross-warp prefix) ----
        unsigned msk[SCPT];
        #pragma unroll
        for (int j = 0; j < SCPT; j++) {
            bool a = ((j < 4) || tv) && (s[j] != 0.0f);
            msk[j] = __ballot_sync(0xffffffffu, a);
            if (lane == 0) s_wcnt[j][wid] = __popc(msk[j]);
        }
        __syncthreads();

        int base[SCPT];
        int cnt;
        {
            int rb = 0;
            #pragma unroll
            for (int jj = 0; jj < SCPT; jj++) {
                int off = 0, rowtot = 0;
                #pragma unroll
                for (int w = 0; w < NWP; w++) {
                    int c = s_wcnt[jj][w];
                    if (w < wid) off += c;
                    rowtot += c;
                }
                base[jj] = rb + off;
                rb += rowtot;
            }
            cnt = rb;
        }

        #pragma unroll
        for (int j = 0; j < SCPT; j++) {
            bool a = ((j < 4) || tv) && (s[j] != 0.0f);
            if (a) s_list[base[j] + __popc(msk[j] & ltmask)] = j * NT + tid;
        }
        __syncthreads();

        // ---- rec: panel-folded ascending adds, unroll-4 batched loads ----
        float rec[SCPT], part[SCPT];
        #pragma unroll
        for (int j = 0; j < SCPT; j++) { rec[j] = 0.0f; part[j] = 0.0f; }

        int curp = 0;
        int i = 0;
        for (; i + 4 <= cnt; i += 4) {
            int m0 = s_list[i + 0], m1 = s_list[i + 1];
            int m2 = s_list[i + 2], m3 = s_list[i + 3];
            const float* w0 = Wrec + (size_t)m0 * NN;
            const float* w1 = Wrec + (size_t)m1 * NN;
            const float* w2 = Wrec + (size_t)m2 * NN;
            const float* w3 = Wrec + (size_t)m3 * NN;
            float v0[SCPT], v1[SCPT], v2[SCPT], v3[SCPT];
            #pragma unroll
            for (int j = 0; j < SCPT; j++) {
                int n = j * NT + tid;
                bool v = (j < 4) || tv;
                v0[j] = v ? w0[n] : 0.0f;
                v1[j] = v ? w1[n] : 0.0f;
                v2[j] = v ? w2[n] : 0.0f;
                v3[j] = v ? w3[n] : 0.0f;
            }
            int p;
            p = m0 / KC; if (p != curp) { flush_panel(rec, part); curp = p; } add_row(part, v0);
            p = m1 / KC; if (p != curp) { flush_panel(rec, part); curp = p; } add_row(part, v1);
            p = m2 / KC; if (p != curp) { flush_panel(rec, part); curp = p; } add_row(part, v2);
            p = m3 / KC; if (p != curp) { flush_panel(rec, part); curp = p; } add_row(part, v3);
        }
        for (; i < cnt; i++) {
            int mr = s_list[i];
            const float* wr = Wrec + (size_t)mr * NN;
            float v0[SCPT];
            #pragma unroll
            for (int j = 0; j < SCPT; j++) {
                int n = j * NT + tid;
                v0[j] = ((j < 4) || tv) ? wr[n] : 0.0f;
            }
            int p = mr / KC;
            if (p != curp) { flush_panel(rec, part); curp = p; }
            add_row(part, v0);
        }
        flush_panel(rec, part);   // final panel fold into rec

        // ---- membrane update + spikes ----
        #pragma unroll
        for (int j = 0; j < SCPT; j++) {
            if ((j < 4) || tv) {
                float cur = __fadd_rn(ffv[j], rec[j]);
                float t1  = __fmul_rn(TAU, m[j]);
                float t2  = __fsub_rn(1.0f, s[j]);
                float t3  = __fmul_rn(t1, t2);
                float mn  = __fadd_rn(t3, cur);
                m[j] = mn;
                s[j] = (mn >= 1.0f) ? 1.0f : 0.0f;
            }
        }
        if (tv)
            out[((size_t)b * T_ + t) * NOUT + tid] = s[4];

        __syncthreads();   // protect s_list/s_wcnt reuse next step
    }
}

// ---------------- launch -----------------------------------------------------
extern "C" void kernel_launch(void* const* d_in, const int* in_sizes, int n_in,
                              void* d_out, int out_size) {
    const float* x  = (const float*)d_in[0];   // [B, T, NIN]
    const float* W1 = (const float*)d_in[1];   // [NN, NIN]
    const float* Wr = (const float*)d_in[2];   // [NN, NN]
    float* out = (float*)d_out;                // [B, T, NOUT]

    {
        size_t n = (size_t)MROWS * KP;
        pad_x_kernel<<<(unsigned)((n + 255) / 256), 256>>>(x);
    }
    {
        size_t n = (size_t)KP * NNP;
        pad_w1t_kernel<<<(unsigned)((n + 255) / 256), 256>>>(W1);
    }

    dim3 ggrid(NNP / BN, MROWS / BM, 3);   // 17 x 200 x 3 slabs
    gemm_slab_kernel<<<ggrid, 256>>>();

    steps_kernel<<<B_, NT>>>(Wr, out);
}